// round 4
// baseline (speedup 1.0000x reference)
#include <cuda_runtime.h>
#include <math.h>

#define BB_ 512
#define NN_ 4096
#define DD_ 128
#define HH_ 8
#define TPREV_ 2048
#define S1_ 4
#define S2_ 8
#define CHUNK_ 512            // tokens per split CTA (2048/4 and 4096/8)
#define PSTRIDE_ 144          // 8 m + 8 l + 128 acc

// ---------------- device scratch (static; no allocations) ----------------
__device__ float g_ht1[BB_ * DD_];
__device__ float g_query[BB_ * DD_];
__device__ float g_part1[BB_ * S1_ * PSTRIDE_];
__device__ float g_part2[BB_ * S2_ * PSTRIDE_];

// ---------------- helpers ----------------
__device__ __forceinline__ float warp_sum(float v) {
    v += __shfl_xor_sync(0xffffffffu, v, 16);
    v += __shfl_xor_sync(0xffffffffu, v, 8);
    v += __shfl_xor_sync(0xffffffffu, v, 4);
    v += __shfl_xor_sync(0xffffffffu, v, 2);
    v += __shfl_xor_sync(0xffffffffu, v, 1);
    return v;
}

__device__ __forceinline__ float blk_sum128(float v, float* red, int lane, int warp) {
    v = warp_sum(v);
    __syncthreads();
    if (lane == 0) red[warp] = v;
    __syncthreads();
    return red[0] + red[1] + red[2] + red[3];
}

// y[r] = sum_j x[j] * Wm[r*128 + j] + bm[r]; 128 threads (4 warps), warp-per-row.
// Per-row arithmetic (lane partial + warp_sum) is identical regardless of warp
// count, so results are bitwise-stable across callers.
__device__ __forceinline__ void gemv128(const float* __restrict__ Wm,
                                        const float* __restrict__ bm,
                                        const float* __restrict__ shx,
                                        float* __restrict__ shy,
                                        int lane, int warp) {
    float4 xv = ((const float4*)shx)[lane];
#pragma unroll 4
    for (int r = warp; r < DD_; r += 4) {
        float4 wv = __ldg(((const float4*)(Wm + r * DD_)) + lane);
        float p = fmaf(wv.x, xv.x, fmaf(wv.y, xv.y, fmaf(wv.z, xv.z, wv.w * xv.w)));
        p = warp_sum(p);
        if (lane == 0) shy[r] = p + bm[r];
    }
}

// ---------------- core online-softmax step ----------------
__device__ __forceinline__ void osm_step(float4 k4, float4 v4, float4 qv,
                                         float& m, float& l, float4& acc) {
    float dt = fmaf(k4.x, qv.x, fmaf(k4.y, qv.y, fmaf(k4.z, qv.z, k4.w * qv.w)));
    dt += __shfl_xor_sync(0xffffffffu, dt, 1);
    dt += __shfl_xor_sync(0xffffffffu, dt, 2);     // head dot (4-lane group)
    float sc = dt * 0.25f;                          // 1/sqrt(16)
    float mn = fmaxf(m, sc);
    float scale = __expf(m - mn);                   // exp(-inf)=0 on first iter
    float p = __expf(sc - mn);
    l = fmaf(l, scale, p);
    acc.x = fmaf(acc.x, scale, p * v4.x);
    acc.y = fmaf(acc.y, scale, p * v4.y);
    acc.z = fmaf(acc.z, scale, p * v4.z);
    acc.w = fmaf(acc.w, scale, p * v4.w);
    m = mn;
}

// store CTA-merged partials
__device__ __forceinline__ void merge_and_store(float m, float l, float4 acc,
                                                float* __restrict__ part,
                                                int b, int s, int nsplit,
                                                int tid, int lane, int warp) {
    __shared__ float sm_m[8][HH_], sm_l[8][HH_];
    __shared__ __align__(16) float sm_acc[8][DD_];
    int head = lane >> 2;
    if ((lane & 3) == 0) { sm_m[warp][head] = m; sm_l[warp][head] = l; }
    ((float4*)sm_acc[warp])[lane] = acc;
    __syncthreads();

    if (tid < DD_) {
        int h = tid >> 4;
        float M = -INFINITY;
#pragma unroll
        for (int w = 0; w < 8; w++) M = fmaxf(M, sm_m[w][h]);
        float L = 0.f, A = 0.f;
#pragma unroll
        for (int w = 0; w < 8; w++) {
            float ms = sm_m[w][h];
            float e = (ms == -INFINITY) ? 0.f : __expf(ms - M);
            L = fmaf(e, sm_l[w][h], L);
            A = fmaf(e, sm_acc[w][tid], A);
        }
        float* pp = part + ((size_t)b * nsplit + s) * PSTRIDE_;
        if ((tid & 15) == 0) { pp[h] = M; pp[8 + h] = L; }
        pp[16 + tid] = A;
    }
}

// ---------------- attn1: unmasked streaming split, q computed inline ----------------
__global__ void __launch_bounds__(256) attn1_split_k(const float* __restrict__ Kv,
                                                     const float* __restrict__ Vv,
                                                     const float* __restrict__ ht,
                                                     const float* __restrict__ W,
                                                     const float* __restrict__ bb) {
    const int s = blockIdx.x, b = blockIdx.y;
    const int tid = threadIdx.x, lane = tid & 31, warp = tid >> 5;

    __shared__ __align__(16) float sht[DD_];
    __shared__ __align__(16) float shq[DD_];
    if (tid < DD_) sht[tid] = __ldg(&ht[b * DD_ + tid]);
    __syncthreads();

    // inline q = W0 * ht + b0 (8 warps, 16 rows each); same per-row math as gemv128
    {
        float4 xv = ((const float4*)sht)[lane];
#pragma unroll 4
        for (int r = warp; r < DD_; r += 8) {
            float4 wv = __ldg(((const float4*)(W + r * DD_)) + lane);
            float p = fmaf(wv.x, xv.x, fmaf(wv.y, xv.y, fmaf(wv.z, xv.z, wv.w * xv.w)));
            p = warp_sum(p);
            if (lane == 0) shq[r] = p + bb[r];
        }
    }
    __syncthreads();

    const float4 qv = ((const float4*)shq)[lane];
    const size_t base4 = ((size_t)b * TPREV_ + (size_t)s * CHUNK_) * (DD_ / 4);
    const float4* Kb = ((const float4*)Kv) + base4;
    const float4* Vb = ((const float4*)Vv) + base4;

    float m = -INFINITY, l = 0.f;
    float4 acc = make_float4(0.f, 0.f, 0.f, 0.f);

#pragma unroll 8
    for (int t = warp; t < CHUNK_; t += 8) {
        float4 k4 = __ldcs(&Kb[t * 32 + lane]);
        float4 v4 = __ldcs(&Vb[t * 32 + lane]);
        osm_step(k4, v4, qv, m, l, acc);
    }
    merge_and_store(m, l, acc, g_part1, b, s, S1_, tid, lane, warp);
}

// ---------------- attn2: masked, with deterministic compaction ----------------
__global__ void __launch_bounds__(256) attn2_split_k(const float* __restrict__ Kv,
                                                     const float* __restrict__ Vv,
                                                     const int* __restrict__ mask) {
    const int s = blockIdx.x, b = blockIdx.y;
    const int tid = threadIdx.x, lane = tid & 31, warp = tid >> 5;

    __shared__ __align__(16) float shq[DD_];
    __shared__ int shidx[CHUNK_];
    __shared__ int warpsum[8];
    __shared__ int shcnt;
    if (tid < DD_) shq[tid] = g_query[b * DD_ + tid];

    // load 2 mask entries per thread
    const int2* mp = (const int2*)(mask + (size_t)b * NN_ + (size_t)s * CHUNK_);
    int2 mv = __ldcs(&mp[tid]);
    int u0 = (mv.x != 1) ? 1 : 0;
    int u1 = (mv.y != 1) ? 1 : 0;
    int cnt = u0 + u1;

    // block-wide exclusive prefix scan (deterministic)
    int pre = cnt;
#pragma unroll
    for (int d = 1; d < 32; d <<= 1) {
        int n = __shfl_up_sync(0xffffffffu, pre, d);
        if (lane >= d) pre += n;
    }
    if (lane == 31) warpsum[warp] = pre;
    __syncthreads();
    if (warp == 0) {
        int w = (lane < 8) ? warpsum[lane] : 0;
        int p = w;
#pragma unroll
        for (int d = 1; d < 8; d <<= 1) {
            int n = __shfl_up_sync(0xffffffffu, p, d);
            if (lane >= d) p += n;
        }
        if (lane < 8) warpsum[lane] = p - w;         // exclusive warp offset
        if (lane == 7) shcnt = p;                    // total unmasked
    }
    __syncthreads();
    int off = warpsum[warp] + (pre - cnt);
    if (u0) shidx[off++] = 2 * tid;
    if (u1) shidx[off] = 2 * tid + 1;
    __syncthreads();

    const int total = shcnt;
    const float4 qv = ((const float4*)shq)[lane];
    const size_t base4 = ((size_t)b * NN_ + (size_t)s * CHUNK_) * (DD_ / 4);
    const float4* Kb = ((const float4*)Kv) + base4;
    const float4* Vb = ((const float4*)Vv) + base4;

    float m = -INFINITY, l = 0.f;
    float4 acc = make_float4(0.f, 0.f, 0.f, 0.f);

#pragma unroll 4
    for (int i = warp; i < total; i += 8) {
        int t = shidx[i];
        float4 k4 = __ldcs(&Kb[t * 32 + lane]);
        float4 v4 = __ldcs(&Vb[t * 32 + lane]);
        osm_step(k4, v4, qv, m, l, acc);
    }
    merge_and_store(m, l, acc, g_part2, b, s, S2_, tid, lane, warp);
}

// ---------------- reduce1: inline q/kself/vself, merge attn1 + self token,
//                  proj W3, residual, LN0, proj W4 -> query
__global__ void __launch_bounds__(128) reduce1_k(const float* __restrict__ ht0,
                                                 const float* __restrict__ W,
                                                 const float* __restrict__ bb,
                                                 const float* __restrict__ lng,
                                                 const float* __restrict__ lnb) {
    int b = blockIdx.x, tid = threadIdx.x, lane = tid & 31, warp = tid >> 5;
    int h = tid >> 4;
    __shared__ __align__(16) float shx[DD_];
    __shared__ __align__(16) float shA[DD_], shB[DD_];
    __shared__ __align__(16) float sq[DD_], sk[DD_], sv[DD_];
    __shared__ float red[4];

    shx[tid] = __ldg(&ht0[b * DD_ + tid]);
    __syncthreads();

    // inline self-token projections (same math as before => bitwise-identical)
    gemv128(W + 0 * DD_ * DD_, bb + 0 * DD_, shx, sq, lane, warp);
    gemv128(W + 1 * DD_ * DD_, bb + 1 * DD_, shx, sk, lane, warp);
    gemv128(W + 2 * DD_ * DD_, bb + 2 * DD_, shx, sv, lane, warp);
    __syncthreads();

    float qk = 0.f;
#pragma unroll
    for (int j = 0; j < 16; j++) qk = fmaf(sq[h * 16 + j], sk[h * 16 + j], qk);
    float M = qk * 0.25f, L = 1.f, A = sv[tid];

    const float* pp = g_part1 + (size_t)b * S1_ * PSTRIDE_;
#pragma unroll
    for (int s = 0; s < S1_; s++) {
        const float* p = pp + s * PSTRIDE_;
        float ms = p[h], ls = p[8 + h], as = p[16 + tid];
        float Mn = fmaxf(M, ms);
        float e0 = __expf(M - Mn);
        float e1 = (ms == -INFINITY) ? 0.f : __expf(ms - Mn);
        A = A * e0 + as * e1;
        L = L * e0 + ls * e1;
        M = Mn;
    }
    shA[tid] = A / L;
    __syncthreads();

    gemv128(W + 3 * DD_ * DD_, bb + 3 * DD_, shA, shB, lane, warp);
    __syncthreads();

    float v = shx[tid] + shB[tid];
    float mean = blk_sum128(v, red, lane, warp) * (1.f / 128.f);
    float dv = v - mean;
    float var = blk_sum128(dv * dv, red, lane, warp) * (1.f / 128.f);
    float ln = dv * rsqrtf(var + 1e-5f) * lng[tid] + lnb[tid];
    g_ht1[b * DD_ + tid] = ln;
    __syncthreads();
    shA[tid] = ln;
    __syncthreads();
    gemv128(W + 4 * DD_ * DD_, bb + 4 * DD_, shA, shB, lane, warp);
    __syncthreads();
    g_query[b * DD_ + tid] = shB[tid];
}

// ---------------- reduce2: merge attn2, proj W5, residual, LN1, FFN, LN2 -> out
__global__ void __launch_bounds__(128) reduce2_k(const float* __restrict__ W,
                                                 const float* __restrict__ bb,
                                                 const float* __restrict__ lng,
                                                 const float* __restrict__ lnb,
                                                 float* __restrict__ out) {
    int b = blockIdx.x, tid = threadIdx.x, lane = tid & 31, warp = tid >> 5;
    int h = tid >> 4;
    __shared__ __align__(16) float shA[DD_], shB[DD_];
    __shared__ float red[4];

    const float* pp = g_part2 + (size_t)b * S2_ * PSTRIDE_;
    float M = -INFINITY, L = 0.f, A = 0.f;
#pragma unroll
    for (int s = 0; s < S2_; s++) {
        const float* p = pp + s * PSTRIDE_;
        float ms = p[h], ls = p[8 + h], as = p[16 + tid];
        float Mn = fmaxf(M, ms);
        float e0 = (M == -INFINITY) ? 0.f : __expf(M - Mn);
        float e1 = (ms == -INFINITY) ? 0.f : __expf(ms - Mn);
        A = A * e0 + as * e1;
        L = L * e0 + ls * e1;
        M = Mn;
    }
    shA[tid] = A / L;
    __syncthreads();

    gemv128(W + 5 * DD_ * DD_, bb + 5 * DD_, shA, shB, lane, warp);
    __syncthreads();

    float v = g_ht1[b * DD_ + tid] + shB[tid];
    float mean = blk_sum128(v, red, lane, warp) * (1.f / 128.f);
    float dv = v - mean;
    float var = blk_sum128(dv * dv, red, lane, warp) * (1.f / 128.f);
    float ht2 = dv * rsqrtf(var + 1e-5f) * lng[DD_ + tid] + lnb[DD_ + tid];
    __syncthreads();
    shA[tid] = ht2;
    __syncthreads();

    gemv128(W + 7 * DD_ * DD_, bb + 7 * DD_, shA, shB, lane, warp);   // FFN in
    __syncthreads();
    shB[tid] = fmaxf(shB[tid], 0.f);                                   // relu
    __syncthreads();
    gemv128(W + 6 * DD_ * DD_, bb + 6 * DD_, shB, shA, lane, warp);   // FFN out
    __syncthreads();

    float v2 = ht2 + shA[tid];
    float mean2 = blk_sum128(v2, red, lane, warp) * (1.f / 128.f);
    float dv2 = v2 - mean2;
    float var2 = blk_sum128(dv2 * dv2, red, lane, warp) * (1.f / 128.f);
    out[b * DD_ + tid] = dv2 * rsqrtf(var2 + 1e-5f) * lng[2 * DD_ + tid] + lnb[2 * DD_ + tid];
}

// ---------------- launch ----------------
extern "C" void kernel_launch(void* const* d_in, const int* in_sizes, int n_in,
                              void* d_out, int out_size) {
    const float* ht    = (const float*)d_in[0];
    const float* key   = (const float*)d_in[1];
    const float* value = (const float*)d_in[2];
    const int*   mask  = (const int*)  d_in[3];
    const float* kprev = (const float*)d_in[4];
    const float* vprev = (const float*)d_in[5];
    const float* W     = (const float*)d_in[6];
    const float* bb    = (const float*)d_in[7];
    const float* ln_g  = (const float*)d_in[8];
    const float* ln_b  = (const float*)d_in[9];
    float* out = (float*)d_out;

    dim3 g1(S1_, BB_);
    attn1_split_k<<<g1, 256>>>(kprev, vprev, ht, W, bb);

    reduce1_k<<<BB_, 128>>>(ht, W, bb, ln_g, ln_b);

    dim3 g2(S2_, BB_);
    attn2_split_k<<<g2, 256>>>(key, value, mask);

    reduce2_k<<<BB_, 128>>>(W, bb, ln_g, ln_b, out);
}

// round 5
// speedup vs baseline: 1.0563x; 1.0563x over previous
#include <cuda_runtime.h>
#include <math.h>

#define BB_ 512
#define NN_ 4096
#define DD_ 128
#define HH_ 8
#define TPREV_ 2048
#define S1_ 4
#define S2_ 8
#define CHUNK_ 512            // tokens per split CTA (2048/4 and 4096/8)
#define PSTRIDE_ 144          // 8 m + 8 l + 128 acc

// ---------------- device scratch (static; no allocations) ----------------
__device__ float g_ht1[BB_ * DD_];
__device__ float g_query[BB_ * DD_];
__device__ float g_part1[BB_ * S1_ * PSTRIDE_];
__device__ float g_part2[BB_ * S2_ * PSTRIDE_];

// ---------------- helpers ----------------
__device__ __forceinline__ float warp_sum(float v) {
    v += __shfl_xor_sync(0xffffffffu, v, 16);
    v += __shfl_xor_sync(0xffffffffu, v, 8);
    v += __shfl_xor_sync(0xffffffffu, v, 4);
    v += __shfl_xor_sync(0xffffffffu, v, 2);
    v += __shfl_xor_sync(0xffffffffu, v, 1);
    return v;
}

// block (256 threads, 8 warps) sum
__device__ __forceinline__ float blk_sum256(float v, float* red, int lane, int warp) {
    v = warp_sum(v);
    __syncthreads();
    if (lane == 0) red[warp] = v;
    __syncthreads();
    float s = 0.f;
#pragma unroll
    for (int w = 0; w < 8; w++) s += red[w];
    return s;
}

// y[r] = sum_j x[j]*Wm[r*128+j] + bm[r]; 256 threads, 8 warps, 16 rows/warp,
// unroll 8 -> only 2 serial L2 rounds. Per-row math (lane partial + warp_sum)
// identical to previous versions.
__device__ __forceinline__ void gemv256(const float* __restrict__ Wm,
                                        const float* __restrict__ bm,
                                        const float* __restrict__ shx,
                                        float* __restrict__ shy,
                                        int lane, int warp) {
    float4 xv = ((const float4*)shx)[lane];
#pragma unroll 8
    for (int r = warp; r < DD_; r += 8) {
        float4 wv = __ldg(((const float4*)(Wm + r * DD_)) + lane);
        float p = fmaf(wv.x, xv.x, fmaf(wv.y, xv.y, fmaf(wv.z, xv.z, wv.w * xv.w)));
        p = warp_sum(p);
        if (lane == 0) shy[r] = p + bm[r];
    }
}

// ---------------- core online-softmax step ----------------
__device__ __forceinline__ void osm_step(float4 k4, float4 v4, float4 qv,
                                         float& m, float& l, float4& acc) {
    float dt = fmaf(k4.x, qv.x, fmaf(k4.y, qv.y, fmaf(k4.z, qv.z, k4.w * qv.w)));
    dt += __shfl_xor_sync(0xffffffffu, dt, 1);
    dt += __shfl_xor_sync(0xffffffffu, dt, 2);     // head dot (4-lane group)
    float sc = dt * 0.25f;                          // 1/sqrt(16)
    float mn = fmaxf(m, sc);
    float scale = __expf(m - mn);                   // exp(-inf)=0 on first iter
    float p = __expf(sc - mn);
    l = fmaf(l, scale, p);
    acc.x = fmaf(acc.x, scale, p * v4.x);
    acc.y = fmaf(acc.y, scale, p * v4.y);
    acc.z = fmaf(acc.z, scale, p * v4.z);
    acc.w = fmaf(acc.w, scale, p * v4.w);
    m = mn;
}

// store CTA-merged partials
__device__ __forceinline__ void merge_and_store(float m, float l, float4 acc,
                                                float* __restrict__ part,
                                                int b, int s, int nsplit,
                                                int tid, int lane, int warp) {
    __shared__ float sm_m[8][HH_], sm_l[8][HH_];
    __shared__ __align__(16) float sm_acc[8][DD_];
    int head = lane >> 2;
    if ((lane & 3) == 0) { sm_m[warp][head] = m; sm_l[warp][head] = l; }
    ((float4*)sm_acc[warp])[lane] = acc;
    __syncthreads();

    if (tid < DD_) {
        int h = tid >> 4;
        float M = -INFINITY;
#pragma unroll
        for (int w = 0; w < 8; w++) M = fmaxf(M, sm_m[w][h]);
        float L = 0.f, A = 0.f;
#pragma unroll
        for (int w = 0; w < 8; w++) {
            float ms = sm_m[w][h];
            float e = (ms == -INFINITY) ? 0.f : __expf(ms - M);
            L = fmaf(e, sm_l[w][h], L);
            A = fmaf(e, sm_acc[w][tid], A);
        }
        float* pp = part + ((size_t)b * nsplit + s) * PSTRIDE_;
        if ((tid & 15) == 0) { pp[h] = M; pp[8 + h] = L; }
        pp[16 + tid] = A;
    }
}

// ---------------- attn1: unmasked streaming split, q computed inline ----------------
__global__ void __launch_bounds__(256) attn1_split_k(const float* __restrict__ Kv,
                                                     const float* __restrict__ Vv,
                                                     const float* __restrict__ ht,
                                                     const float* __restrict__ W,
                                                     const float* __restrict__ bb) {
    const int s = blockIdx.x, b = blockIdx.y;
    const int tid = threadIdx.x, lane = tid & 31, warp = tid >> 5;

    __shared__ __align__(16) float sht[DD_];
    __shared__ __align__(16) float shq[DD_];
    if (tid < DD_) sht[tid] = __ldg(&ht[b * DD_ + tid]);
    __syncthreads();

    // inline q = W0 * ht + b0 (8 warps, 16 rows each, unroll 8 => 2 L2 rounds)
    gemv256(W, bb, sht, shq, lane, warp);
    __syncthreads();

    const float4 qv = ((const float4*)shq)[lane];
    const size_t base4 = ((size_t)b * TPREV_ + (size_t)s * CHUNK_) * (DD_ / 4);
    const float4* Kb = ((const float4*)Kv) + base4;
    const float4* Vb = ((const float4*)Vv) + base4;

    float m = -INFINITY, l = 0.f;
    float4 acc = make_float4(0.f, 0.f, 0.f, 0.f);

#pragma unroll 8
    for (int t = warp; t < CHUNK_; t += 8) {
        float4 k4 = __ldcs(&Kb[t * 32 + lane]);
        float4 v4 = __ldcs(&Vb[t * 32 + lane]);
        osm_step(k4, v4, qv, m, l, acc);
    }
    merge_and_store(m, l, acc, g_part1, b, s, S1_, tid, lane, warp);
}

// ---------------- attn2: masked, with deterministic compaction ----------------
__global__ void __launch_bounds__(256) attn2_split_k(const float* __restrict__ Kv,
                                                     const float* __restrict__ Vv,
                                                     const int* __restrict__ mask) {
    const int s = blockIdx.x, b = blockIdx.y;
    const int tid = threadIdx.x, lane = tid & 31, warp = tid >> 5;

    __shared__ __align__(16) float shq[DD_];
    __shared__ int shidx[CHUNK_];
    __shared__ int warpsum[8];
    __shared__ int shcnt;
    if (tid < DD_) shq[tid] = g_query[b * DD_ + tid];

    // load 2 mask entries per thread
    const int2* mp = (const int2*)(mask + (size_t)b * NN_ + (size_t)s * CHUNK_);
    int2 mv = __ldcs(&mp[tid]);
    int u0 = (mv.x != 1) ? 1 : 0;
    int u1 = (mv.y != 1) ? 1 : 0;
    int cnt = u0 + u1;

    // block-wide exclusive prefix scan (deterministic)
    int pre = cnt;
#pragma unroll
    for (int d = 1; d < 32; d <<= 1) {
        int n = __shfl_up_sync(0xffffffffu, pre, d);
        if (lane >= d) pre += n;
    }
    if (lane == 31) warpsum[warp] = pre;
    __syncthreads();
    if (warp == 0) {
        int w = (lane < 8) ? warpsum[lane] : 0;
        int p = w;
#pragma unroll
        for (int d = 1; d < 8; d <<= 1) {
            int n = __shfl_up_sync(0xffffffffu, p, d);
            if (lane >= d) p += n;
        }
        if (lane < 8) warpsum[lane] = p - w;         // exclusive warp offset
        if (lane == 7) shcnt = p;                    // total unmasked
    }
    __syncthreads();
    int off = warpsum[warp] + (pre - cnt);
    if (u0) shidx[off++] = 2 * tid;
    if (u1) shidx[off] = 2 * tid + 1;
    __syncthreads();

    const int total = shcnt;
    const float4 qv = ((const float4*)shq)[lane];
    const size_t base4 = ((size_t)b * NN_ + (size_t)s * CHUNK_) * (DD_ / 4);
    const float4* Kb = ((const float4*)Kv) + base4;
    const float4* Vb = ((const float4*)Vv) + base4;

    float m = -INFINITY, l = 0.f;
    float4 acc = make_float4(0.f, 0.f, 0.f, 0.f);

#pragma unroll 4
    for (int i = warp; i < total; i += 8) {
        int t = shidx[i];
        float4 k4 = __ldcs(&Kb[t * 32 + lane]);
        float4 v4 = __ldcs(&Vb[t * 32 + lane]);
        osm_step(k4, v4, qv, m, l, acc);
    }
    merge_and_store(m, l, acc, g_part2, b, s, S2_, tid, lane, warp);
}

// ---------------- reduce1: inline q/kself/vself, merge attn1 + self token,
//                  proj W3, residual, LN0, proj W4 -> query   (256 threads)
__global__ void __launch_bounds__(256) reduce1_k(const float* __restrict__ ht0,
                                                 const float* __restrict__ W,
                                                 const float* __restrict__ bb,
                                                 const float* __restrict__ lng,
                                                 const float* __restrict__ lnb) {
    int b = blockIdx.x, tid = threadIdx.x, lane = tid & 31, warp = tid >> 5;
    __shared__ __align__(16) float shx[DD_];
    __shared__ __align__(16) float shA[DD_], shB[DD_];
    __shared__ __align__(16) float sq[DD_], sk[DD_], sv[DD_];
    __shared__ float red[8];

    if (tid < DD_) shx[tid] = __ldg(&ht0[b * DD_ + tid]);
    __syncthreads();

    gemv256(W + 0 * DD_ * DD_, bb + 0 * DD_, shx, sq, lane, warp);
    gemv256(W + 1 * DD_ * DD_, bb + 1 * DD_, shx, sk, lane, warp);
    gemv256(W + 2 * DD_ * DD_, bb + 2 * DD_, shx, sv, lane, warp);
    __syncthreads();

    if (tid < DD_) {
        int h = tid >> 4;
        float qk = 0.f;
#pragma unroll
        for (int j = 0; j < 16; j++) qk = fmaf(sq[h * 16 + j], sk[h * 16 + j], qk);
        float M = qk * 0.25f, L = 1.f, A = sv[tid];

        const float* pp = g_part1 + (size_t)b * S1_ * PSTRIDE_;
#pragma unroll
        for (int s = 0; s < S1_; s++) {
            const float* p = pp + s * PSTRIDE_;
            float ms = p[h], ls = p[8 + h], as = p[16 + tid];
            float Mn = fmaxf(M, ms);
            float e0 = __expf(M - Mn);
            float e1 = (ms == -INFINITY) ? 0.f : __expf(ms - Mn);
            A = A * e0 + as * e1;
            L = L * e0 + ls * e1;
            M = Mn;
        }
        shA[tid] = A / L;
    }
    __syncthreads();

    gemv256(W + 3 * DD_ * DD_, bb + 3 * DD_, shA, shB, lane, warp);
    __syncthreads();

    float v = (tid < DD_) ? (shx[tid] + shB[tid]) : 0.f;
    float mean = blk_sum256(v, red, lane, warp) * (1.f / 128.f);
    float dv = (tid < DD_) ? (v - mean) : 0.f;
    float var = blk_sum256(dv * dv, red, lane, warp) * (1.f / 128.f);
    if (tid < DD_) {
        float ln = dv * rsqrtf(var + 1e-5f) * lng[tid] + lnb[tid];
        g_ht1[b * DD_ + tid] = ln;
        shA[tid] = ln;
    }
    __syncthreads();
    gemv256(W + 4 * DD_ * DD_, bb + 4 * DD_, shA, shB, lane, warp);
    __syncthreads();
    if (tid < DD_) g_query[b * DD_ + tid] = shB[tid];
}

// ---------------- reduce2: merge attn2, proj W5, residual, LN1, FFN, LN2 -> out
//                  (256 threads)
__global__ void __launch_bounds__(256) reduce2_k(const float* __restrict__ W,
                                                 const float* __restrict__ bb,
                                                 const float* __restrict__ lng,
                                                 const float* __restrict__ lnb,
                                                 float* __restrict__ out) {
    int b = blockIdx.x, tid = threadIdx.x, lane = tid & 31, warp = tid >> 5;
    __shared__ __align__(16) float shA[DD_], shB[DD_];
    __shared__ float red[8];

    if (tid < DD_) {
        int h = tid >> 4;
        const float* pp = g_part2 + (size_t)b * S2_ * PSTRIDE_;
        float M = -INFINITY, L = 0.f, A = 0.f;
#pragma unroll
        for (int s = 0; s < S2_; s++) {
            const float* p = pp + s * PSTRIDE_;
            float ms = p[h], ls = p[8 + h], as = p[16 + tid];
            float Mn = fmaxf(M, ms);
            float e0 = (M == -INFINITY) ? 0.f : __expf(M - Mn);
            float e1 = (ms == -INFINITY) ? 0.f : __expf(ms - Mn);
            A = A * e0 + as * e1;
            L = L * e0 + ls * e1;
            M = Mn;
        }
        shA[tid] = A / L;
    }
    __syncthreads();

    gemv256(W + 5 * DD_ * DD_, bb + 5 * DD_, shA, shB, lane, warp);
    __syncthreads();

    float v = (tid < DD_) ? (g_ht1[b * DD_ + tid] + shB[tid]) : 0.f;
    float mean = blk_sum256(v, red, lane, warp) * (1.f / 128.f);
    float dv = (tid < DD_) ? (v - mean) : 0.f;
    float var = blk_sum256(dv * dv, red, lane, warp) * (1.f / 128.f);
    float ht2 = 0.f;
    if (tid < DD_) {
        ht2 = dv * rsqrtf(var + 1e-5f) * lng[DD_ + tid] + lnb[DD_ + tid];
        shA[tid] = ht2;
    }
    __syncthreads();

    gemv256(W + 7 * DD_ * DD_, bb + 7 * DD_, shA, shB, lane, warp);   // FFN in
    __syncthreads();
    if (tid < DD_) shB[tid] = fmaxf(shB[tid], 0.f);                    // relu
    __syncthreads();
    gemv256(W + 6 * DD_ * DD_, bb + 6 * DD_, shB, shA, lane, warp);   // FFN out
    __syncthreads();

    float v2 = (tid < DD_) ? (ht2 + shA[tid]) : 0.f;
    float mean2 = blk_sum256(v2, red, lane, warp) * (1.f / 128.f);
    float dv2 = (tid < DD_) ? (v2 - mean2) : 0.f;
    float var2 = blk_sum256(dv2 * dv2, red, lane, warp) * (1.f / 128.f);
    if (tid < DD_)
        out[b * DD_ + tid] = dv2 * rsqrtf(var2 + 1e-5f) * lng[2 * DD_ + tid] + lnb[2 * DD_ + tid];
}

// ---------------- launch ----------------
extern "C" void kernel_launch(void* const* d_in, const int* in_sizes, int n_in,
                              void* d_out, int out_size) {
    const float* ht    = (const float*)d_in[0];
    const float* key   = (const float*)d_in[1];
    const float* value = (const float*)d_in[2];
    const int*   mask  = (const int*)  d_in[3];
    const float* kprev = (const float*)d_in[4];
    const float* vprev = (const float*)d_in[5];
    const float* W     = (const float*)d_in[6];
    const float* bb    = (const float*)d_in[7];
    const float* ln_g  = (const float*)d_in[8];
    const float* ln_b  = (const float*)d_in[9];
    float* out = (float*)d_out;

    dim3 g1(S1_, BB_);
    attn1_split_k<<<g1, 256>>>(kprev, vprev, ht, W, bb);

    reduce1_k<<<BB_, 256>>>(ht, W, bb, ln_g, ln_b);

    dim3 g2(S2_, BB_);
    attn2_split_k<<<g2, 256>>>(key, value, mask);

    reduce2_k<<<BB_, 256>>>(W, bb, ln_g, ln_b, out);
}

// round 6
// speedup vs baseline: 1.0935x; 1.0352x over previous
#include <cuda_runtime.h>
#include <math.h>

#define BB_ 512
#define NN_ 4096
#define DD_ 128
#define HH_ 8
#define TPREV_ 2048
#define S1_ 4
#define S2_ 8
#define CHUNK_ 512            // tokens per split CTA (2048/4 and 4096/8)
#define PSTRIDE_ 144          // 8 m + 8 l + 128 acc

// ---------------- device scratch (static; no allocations) ----------------
__device__ float g_ht1[BB_ * DD_];
__device__ float g_query[BB_ * DD_];
__device__ float g_part1[BB_ * S1_ * PSTRIDE_];
__device__ float g_part2[BB_ * S2_ * PSTRIDE_];
__device__ int   g_cnt1[BB_];    // zero-init; self-resetting each call
__device__ int   g_cnt2[BB_];

// ---------------- helpers ----------------
__device__ __forceinline__ float warp_sum(float v) {
    v += __shfl_xor_sync(0xffffffffu, v, 16);
    v += __shfl_xor_sync(0xffffffffu, v, 8);
    v += __shfl_xor_sync(0xffffffffu, v, 4);
    v += __shfl_xor_sync(0xffffffffu, v, 2);
    v += __shfl_xor_sync(0xffffffffu, v, 1);
    return v;
}

// block (256 threads, 8 warps) sum
__device__ __forceinline__ float blk_sum256(float v, float* red, int lane, int warp) {
    v = warp_sum(v);
    __syncthreads();
    if (lane == 0) red[warp] = v;
    __syncthreads();
    float s = 0.f;
#pragma unroll
    for (int w = 0; w < 8; w++) s += red[w];
    return s;
}

// y[r] = sum_j x[j]*Wm[r*128+j] + bm[r]; 256 threads, 8 warps, 16 rows/warp.
// Per-row math (lane partial + warp_sum) is caller-invariant => bitwise stable.
__device__ __forceinline__ void gemv256(const float* __restrict__ Wm,
                                        const float* __restrict__ bm,
                                        const float* __restrict__ shx,
                                        float* __restrict__ shy,
                                        int lane, int warp) {
    float4 xv = ((const float4*)shx)[lane];
#pragma unroll 8
    for (int r = warp; r < DD_; r += 8) {
        float4 wv = __ldg(((const float4*)(Wm + r * DD_)) + lane);
        float p = fmaf(wv.x, xv.x, fmaf(wv.y, xv.y, fmaf(wv.z, xv.z, wv.w * xv.w)));
        p = warp_sum(p);
        if (lane == 0) shy[r] = p + bm[r];
    }
}

// ---------------- core online-softmax step ----------------
__device__ __forceinline__ void osm_step(float4 k4, float4 v4, float4 qv,
                                         float& m, float& l, float4& acc) {
    float dt = fmaf(k4.x, qv.x, fmaf(k4.y, qv.y, fmaf(k4.z, qv.z, k4.w * qv.w)));
    dt += __shfl_xor_sync(0xffffffffu, dt, 1);
    dt += __shfl_xor_sync(0xffffffffu, dt, 2);     // head dot (4-lane group)
    float sc = dt * 0.25f;                          // 1/sqrt(16)
    float mn = fmaxf(m, sc);
    float scale = __expf(m - mn);                   // exp(-inf)=0 on first iter
    float p = __expf(sc - mn);
    l = fmaf(l, scale, p);
    acc.x = fmaf(acc.x, scale, p * v4.x);
    acc.y = fmaf(acc.y, scale, p * v4.y);
    acc.z = fmaf(acc.z, scale, p * v4.z);
    acc.w = fmaf(acc.w, scale, p * v4.w);
    m = mn;
}

// CTA-internal merge of 8 warp-partials, store to global partials
__device__ __forceinline__ void merge_and_store(float m, float l, float4 acc,
                                                float* __restrict__ part,
                                                int b, int s, int nsplit,
                                                int tid, int lane, int warp) {
    __shared__ float sm_m[8][HH_], sm_l[8][HH_];
    __shared__ __align__(16) float sm_acc[8][DD_];
    int head = lane >> 2;
    if ((lane & 3) == 0) { sm_m[warp][head] = m; sm_l[warp][head] = l; }
    ((float4*)sm_acc[warp])[lane] = acc;
    __syncthreads();

    if (tid < DD_) {
        int h = tid >> 4;
        float M = -INFINITY;
#pragma unroll
        for (int w = 0; w < 8; w++) M = fmaxf(M, sm_m[w][h]);
        float L = 0.f, A = 0.f;
#pragma unroll
        for (int w = 0; w < 8; w++) {
            float ms = sm_m[w][h];
            float e = (ms == -INFINITY) ? 0.f : __expf(ms - M);
            L = fmaf(e, sm_l[w][h], L);
            A = fmaf(e, sm_acc[w][tid], A);
        }
        float* pp = part + ((size_t)b * nsplit + s) * PSTRIDE_;
        if ((tid & 15) == 0) { pp[h] = M; pp[8 + h] = L; }
        pp[16 + tid] = A;
    }
}

// returns true (for all 256 threads) iff this CTA is the last arrival for batch b
__device__ __forceinline__ bool last_cta_arrival(int* cnt, int b, int nsplit,
                                                 int tid, int* shflag) {
    __threadfence();                 // make this CTA's partial writes visible
    __syncthreads();                 // all threads fenced before the atomic
    if (tid == 0) {
        int old = atomicAdd(&cnt[b], 1);
        *shflag = (old == nsplit - 1) ? 1 : 0;
    }
    __syncthreads();
    bool last = (*shflag != 0);
    if (last) __threadfence();       // acquire: other CTAs' partials now visible
    return last;
}

// ---------------- attn1 + fused reduce1 ----------------
__global__ void __launch_bounds__(256) attn1_split_k(const float* __restrict__ Kv,
                                                     const float* __restrict__ Vv,
                                                     const float* __restrict__ ht,
                                                     const float* __restrict__ W,
                                                     const float* __restrict__ bb,
                                                     const float* __restrict__ lng,
                                                     const float* __restrict__ lnb) {
    const int s = blockIdx.x, b = blockIdx.y;
    const int tid = threadIdx.x, lane = tid & 31, warp = tid >> 5;

    __shared__ __align__(16) float sht[DD_];
    __shared__ __align__(16) float shq[DD_];
    __shared__ int shflag;
    if (tid < DD_) sht[tid] = __ldg(&ht[b * DD_ + tid]);
    __syncthreads();

    // inline q = W0 * ht + b0
    gemv256(W, bb, sht, shq, lane, warp);
    __syncthreads();

    const float4 qv = ((const float4*)shq)[lane];
    const size_t base4 = ((size_t)b * TPREV_ + (size_t)s * CHUNK_) * (DD_ / 4);
    const float4* Kb = ((const float4*)Kv) + base4;
    const float4* Vb = ((const float4*)Vv) + base4;

    float m = -INFINITY, l = 0.f;
    float4 acc = make_float4(0.f, 0.f, 0.f, 0.f);

#pragma unroll 8
    for (int t = warp; t < CHUNK_; t += 8) {
        float4 k4 = __ldcs(&Kb[t * 32 + lane]);
        float4 v4 = __ldcs(&Vb[t * 32 + lane]);
        osm_step(k4, v4, qv, m, l, acc);
    }
    merge_and_store(m, l, acc, g_part1, b, s, S1_, tid, lane, warp);

    // ---- fan-in: last split CTA of this batch performs reduce1 ----
    if (!last_cta_arrival(g_cnt1, b, S1_, tid, &shflag)) return;

    __shared__ __align__(16) float shA[DD_], shB[DD_];
    __shared__ __align__(16) float sk[DD_], sv[DD_];
    __shared__ float red[8];

    // kself/vself projections (q already in shq, same math as reduce1 had)
    gemv256(W + 1 * DD_ * DD_, bb + 1 * DD_, sht, sk, lane, warp);
    gemv256(W + 2 * DD_ * DD_, bb + 2 * DD_, sht, sv, lane, warp);
    __syncthreads();

    if (tid < DD_) {
        int h = tid >> 4;
        float qk = 0.f;
#pragma unroll
        for (int j = 0; j < 16; j++) qk = fmaf(shq[h * 16 + j], sk[h * 16 + j], qk);
        float M = qk * 0.25f, L = 1.f, A = sv[tid];

        const float* pp = g_part1 + (size_t)b * S1_ * PSTRIDE_;
#pragma unroll
        for (int sp = 0; sp < S1_; sp++) {
            const float* p = pp + sp * PSTRIDE_;
            float ms = p[h], ls = p[8 + h], as = p[16 + tid];
            float Mn = fmaxf(M, ms);
            float e0 = __expf(M - Mn);
            float e1 = (ms == -INFINITY) ? 0.f : __expf(ms - Mn);
            A = A * e0 + as * e1;
            L = L * e0 + ls * e1;
            M = Mn;
        }
        shA[tid] = A / L;
    }
    __syncthreads();

    gemv256(W + 3 * DD_ * DD_, bb + 3 * DD_, shA, shB, lane, warp);
    __syncthreads();

    float v = (tid < DD_) ? (sht[tid] + shB[tid]) : 0.f;
    float mean = blk_sum256(v, red, lane, warp) * (1.f / 128.f);
    float dv = (tid < DD_) ? (v - mean) : 0.f;
    float var = blk_sum256(dv * dv, red, lane, warp) * (1.f / 128.f);
    if (tid < DD_) {
        float ln = dv * rsqrtf(var + 1e-5f) * lng[tid] + lnb[tid];
        g_ht1[b * DD_ + tid] = ln;
        shA[tid] = ln;
    }
    __syncthreads();
    gemv256(W + 4 * DD_ * DD_, bb + 4 * DD_, shA, shB, lane, warp);
    __syncthreads();
    if (tid < DD_) g_query[b * DD_ + tid] = shB[tid];
    if (tid == 0) g_cnt1[b] = 0;      // reset for next graph replay
}

// ---------------- attn2 (masked + compaction) + fused reduce2 ----------------
__global__ void __launch_bounds__(256) attn2_split_k(const float* __restrict__ Kv,
                                                     const float* __restrict__ Vv,
                                                     const int* __restrict__ mask,
                                                     const float* __restrict__ W,
                                                     const float* __restrict__ bb,
                                                     const float* __restrict__ lng,
                                                     const float* __restrict__ lnb,
                                                     float* __restrict__ out) {
    const int s = blockIdx.x, b = blockIdx.y;
    const int tid = threadIdx.x, lane = tid & 31, warp = tid >> 5;

    __shared__ __align__(16) float shq[DD_];
    __shared__ int shidx[CHUNK_];
    __shared__ int warpsum[8];
    __shared__ int shcnt;
    __shared__ int shflag;
    if (tid < DD_) shq[tid] = g_query[b * DD_ + tid];

    // load 2 mask entries per thread
    const int2* mp = (const int2*)(mask + (size_t)b * NN_ + (size_t)s * CHUNK_);
    int2 mv = __ldcs(&mp[tid]);
    int u0 = (mv.x != 1) ? 1 : 0;
    int u1 = (mv.y != 1) ? 1 : 0;
    int cnt = u0 + u1;

    // block-wide exclusive prefix scan (deterministic)
    int pre = cnt;
#pragma unroll
    for (int d = 1; d < 32; d <<= 1) {
        int n = __shfl_up_sync(0xffffffffu, pre, d);
        if (lane >= d) pre += n;
    }
    if (lane == 31) warpsum[warp] = pre;
    __syncthreads();
    if (warp == 0) {
        int w = (lane < 8) ? warpsum[lane] : 0;
        int p = w;
#pragma unroll
        for (int d = 1; d < 8; d <<= 1) {
            int n = __shfl_up_sync(0xffffffffu, p, d);
            if (lane >= d) p += n;
        }
        if (lane < 8) warpsum[lane] = p - w;         // exclusive warp offset
        if (lane == 7) shcnt = p;                    // total unmasked
    }
    __syncthreads();
    int off = warpsum[warp] + (pre - cnt);
    if (u0) shidx[off++] = 2 * tid;
    if (u1) shidx[off] = 2 * tid + 1;
    __syncthreads();

    const int total = shcnt;
    const float4 qv = ((const float4*)shq)[lane];
    const size_t base4 = ((size_t)b * NN_ + (size_t)s * CHUNK_) * (DD_ / 4);
    const float4* Kb = ((const float4*)Kv) + base4;
    const float4* Vb = ((const float4*)Vv) + base4;

    float m = -INFINITY, l = 0.f;
    float4 acc = make_float4(0.f, 0.f, 0.f, 0.f);

#pragma unroll 4
    for (int i = warp; i < total; i += 8) {
        int t = shidx[i];
        float4 k4 = __ldcs(&Kb[t * 32 + lane]);
        float4 v4 = __ldcs(&Vb[t * 32 + lane]);
        osm_step(k4, v4, qv, m, l, acc);
    }
    merge_and_store(m, l, acc, g_part2, b, s, S2_, tid, lane, warp);

    // ---- fan-in: last split CTA of this batch performs reduce2 ----
    if (!last_cta_arrival(g_cnt2, b, S2_, tid, &shflag)) return;

    __shared__ __align__(16) float shA[DD_], shB[DD_];
    __shared__ float red[8];

    if (tid < DD_) {
        int h = tid >> 4;
        const float* pp = g_part2 + (size_t)b * S2_ * PSTRIDE_;
        float M = -INFINITY, L = 0.f, A = 0.f;
#pragma unroll
        for (int sp = 0; sp < S2_; sp++) {
            const float* p = pp + sp * PSTRIDE_;
            float ms = p[h], ls = p[8 + h], as = p[16 + tid];
            float Mn = fmaxf(M, ms);
            float e0 = (M == -INFINITY) ? 0.f : __expf(M - Mn);
            float e1 = (ms == -INFINITY) ? 0.f : __expf(ms - Mn);
            A = A * e0 + as * e1;
            L = L * e0 + ls * e1;
            M = Mn;
        }
        shA[tid] = A / L;
    }
    __syncthreads();

    gemv256(W + 5 * DD_ * DD_, bb + 5 * DD_, shA, shB, lane, warp);
    __syncthreads();

    float v = (tid < DD_) ? (g_ht1[b * DD_ + tid] + shB[tid]) : 0.f;
    float mean = blk_sum256(v, red, lane, warp) * (1.f / 128.f);
    float dv = (tid < DD_) ? (v - mean) : 0.f;
    float var = blk_sum256(dv * dv, red, lane, warp) * (1.f / 128.f);
    float ht2 = 0.f;
    if (tid < DD_) {
        ht2 = dv * rsqrtf(var + 1e-5f) * lng[DD_ + tid] + lnb[DD_ + tid];
        shA[tid] = ht2;
    }
    __syncthreads();

    gemv256(W + 7 * DD_ * DD_, bb + 7 * DD_, shA, shB, lane, warp);   // FFN in
    __syncthreads();
    if (tid < DD_) shB[tid] = fmaxf(shB[tid], 0.f);                    // relu
    __syncthreads();
    gemv256(W + 6 * DD_ * DD_, bb + 6 * DD_, shB, shA, lane, warp);   // FFN out
    __syncthreads();

    float v2 = (tid < DD_) ? (ht2 + shA[tid]) : 0.f;
    float mean2 = blk_sum256(v2, red, lane, warp) * (1.f / 128.f);
    float dv2 = (tid < DD_) ? (v2 - mean2) : 0.f;
    float var2 = blk_sum256(dv2 * dv2, red, lane, warp) * (1.f / 128.f);
    if (tid < DD_)
        out[b * DD_ + tid] = dv2 * rsqrtf(var2 + 1e-5f) * lng[2 * DD_ + tid] + lnb[2 * DD_ + tid];
    if (tid == 0) g_cnt2[b] = 0;      // reset for next graph replay
}

// ---------------- launch ----------------
extern "C" void kernel_launch(void* const* d_in, const int* in_sizes, int n_in,
                              void* d_out, int out_size) {
    const float* ht    = (const float*)d_in[0];
    const float* key   = (const float*)d_in[1];
    const float* value = (const float*)d_in[2];
    const int*   mask  = (const int*)  d_in[3];
    const float* kprev = (const float*)d_in[4];
    const float* vprev = (const float*)d_in[5];
    const float* W     = (const float*)d_in[6];
    const float* bb    = (const float*)d_in[7];
    const float* ln_g  = (const float*)d_in[8];
    const float* ln_b  = (const float*)d_in[9];
    float* out = (float*)d_out;

    dim3 g1(S1_, BB_);
    attn1_split_k<<<g1, 256>>>(kprev, vprev, ht, W, bb, ln_g, ln_b);

    dim3 g2(S2_, BB_);
    attn2_split_k<<<g2, 256>>>(key, value, mask, W, bb, ln_g, ln_b, out);
}